// round 1
// baseline (speedup 1.0000x reference)
#include <cuda_runtime.h>
#include <cstdint>

#define NN 100000
#define NE 1600000
#define OUT_DECE (NN)
#define OUT_POS  (NN + NE)
#define OUT_VEL  (NN + NE + NN)
#define BLK 32

typedef unsigned long long ull;

// Scratch (device-global: no allocations allowed)
__device__ float4 g_agg[2 * NN];   // [0,NN): sender sums {e0,e1,e2,count}; [NN,2NN): receiver sums
__device__ float  g_prep[40];      // [0..2]=c_edge, [3]=d_edge, [4..35]=p(node dec), [36]=q

// ---------------- packed f32x2 helpers ----------------
__device__ __forceinline__ ull pk2(float lo, float hi) {
    ull r;
    asm("mov.b64 %0, {%1, %2};" : "=l"(r) : "r"(__float_as_uint(lo)), "r"(__float_as_uint(hi)));
    return r;
}
__device__ __forceinline__ void upk2(ull v, float& lo, float& hi) {
    unsigned a, b;
    asm("mov.b64 {%0, %1}, %2;" : "=r"(a), "=r"(b) : "l"(v));
    lo = __uint_as_float(a); hi = __uint_as_float(b);
}
__device__ __forceinline__ ull f2fma(ull a, ull b, ull c) {
    ull d;
    asm("fma.rn.f32x2 %0, %1, %2, %3;" : "=l"(d) : "l"(a), "l"(b), "l"(c));
    return d;
}
__device__ __forceinline__ ull cpk(float x) {
    unsigned u = __float_as_uint(x);
    return (((ull)u) << 32) | (ull)u;
}

// ---------------- tiny precompute kernel ----------------
__global__ void prep_kernel(const float* __restrict__ eW, const float* __restrict__ eb,
                            const float* __restrict__ decEW, const float* __restrict__ decEb,
                            const float* __restrict__ noW, const float* __restrict__ nob,
                            const float* __restrict__ decNW, const float* __restrict__ decNb) {
    int t = threadIdx.x;
    if (t < 3) {
        float s = 0.f;
        for (int c = 0; c < 10; c++) s += eW[t * 10 + c] * decEW[c];
        g_prep[t] = s;
    } else if (t == 3) {
        float s = decEb[0];
        for (int c = 0; c < 10; c++) s += eb[c] * decEW[c];
        g_prep[3] = s;
    } else if (t >= 4 && t < 36) {
        int j = t - 4;
        float s = 0.f;
        for (int c = 0; c < 10; c++) s += noW[j * 10 + c] * decNW[c];
        g_prep[t] = s;
    } else if (t == 36) {
        float s = decNb[0];
        for (int c = 0; c < 10; c++) s += nob[c] * decNW[c];
        g_prep[36] = s;
    }
}

__global__ void zero_kernel() {
    int i = blockIdx.x * blockDim.x + threadIdx.x;
    if (i < 2 * NN) g_agg[i] = make_float4(0.f, 0.f, 0.f, 0.f);
}

// ---------------- edge kernel: dec_e + raw segment sums ----------------
__global__ void edge_kernel(const float* __restrict__ edges,
                            const int* __restrict__ senders,
                            const int* __restrict__ receivers,
                            float* __restrict__ out) {
    int e = blockIdx.x * blockDim.x + threadIdx.x;
    if (e >= NE) return;
    float e0 = edges[3 * e + 0];
    float e1 = edges[3 * e + 1];
    float e2 = edges[3 * e + 2];
    int s = senders[e];
    int r = receivers[e];
    float c0 = g_prep[0], c1 = g_prep[1], c2 = g_prep[2], d = g_prep[3];
    out[OUT_DECE + e] = fmaf(e0, c0, fmaf(e1, c1, fmaf(e2, c2, d)));

    float4* ps = &g_agg[s];
    float4* pr = &g_agg[NN + r];
    asm volatile("red.global.add.v4.f32 [%0], {%1, %2, %3, %4};"
                 :: "l"(ps), "f"(e0), "f"(e1), "f"(e2), "f"(1.0f) : "memory");
    asm volatile("red.global.add.v4.f32 [%0], {%1, %2, %3, %4};"
                 :: "l"(pr), "f"(e0), "f"(e1), "f"(e2), "f"(1.0f) : "memory");
}

// ---------------- ODE kernel ----------------
// 32x32 matmul: h = vec @ W + b, vec read from per-thread smem column (f32x2 pairs),
// weights broadcast from smem via 128-bit loads, packed-f32x2 FMA.
__device__ __forceinline__ void mm32(const float* __restrict__ sW,
                                     const ull* __restrict__ sB,
                                     const ull* __restrict__ vec, int tid, ull h[16]) {
#pragma unroll
    for (int p = 0; p < 16; p++) h[p] = sB[p];
#pragma unroll 1
    for (int ii = 0; ii < 16; ++ii) {
        float lo, hi;
        upk2(vec[ii * BLK + tid], lo, hi);
        ull vlo = pk2(lo, lo);
        ull vhi = pk2(hi, hi);
        const ulonglong2* w0 = reinterpret_cast<const ulonglong2*>(sW + ii * 64);
        const ulonglong2* w1 = reinterpret_cast<const ulonglong2*>(sW + ii * 64 + 32);
#pragma unroll
        for (int q = 0; q < 8; q++) {
            ulonglong2 a = w0[q];
            h[2 * q]     = f2fma(a.x, vlo, h[2 * q]);
            h[2 * q + 1] = f2fma(a.y, vlo, h[2 * q + 1]);
        }
#pragma unroll
        for (int q = 0; q < 8; q++) {
            ulonglong2 a = w1[q];
            h[2 * q]     = f2fma(a.x, vhi, h[2 * q]);
            h[2 * q + 1] = f2fma(a.y, vhi, h[2 * q + 1]);
        }
    }
}

// f(y) = relu(y@W1+b1)@W2+b2 ; input in slot (smem), output in out[] regs.
__device__ __forceinline__ void odef(const float* __restrict__ sW1, const float* __restrict__ sW2,
                                     const ull* __restrict__ sB1, const ull* __restrict__ sB2,
                                     ull* __restrict__ slot, int tid, ull out[16]) {
    ull h[16];
    mm32(sW1, sB1, slot, tid, h);
#pragma unroll
    for (int p = 0; p < 16; p++) {
        float lo, hi;
        upk2(h[p], lo, hi);
        slot[p * BLK + tid] = pk2(fmaxf(lo, 0.f), fmaxf(hi, 0.f));
    }
    mm32(sW2, sB2, slot, tid, out);
}

__global__ __launch_bounds__(BLK)
void ode_kernel(const float* __restrict__ nodes, const float* __restrict__ gl,
                const float* __restrict__ encNW, const float* __restrict__ encNb,
                const float* __restrict__ encEW, const float* __restrict__ encEb,
                const float* __restrict__ W1, const float* __restrict__ b1,
                const float* __restrict__ W2, const float* __restrict__ b2,
                float* __restrict__ out) {
    __shared__ __align__(16) float sW1[1024];
    __shared__ __align__(16) float sW2[1024];
    __shared__ ull sB1[16];
    __shared__ ull sB2[16];
    __shared__ ull sTmp[16 * BLK];
    __shared__ ull sK[4 * 16 * BLK];

    int tid = threadIdx.x;
    for (int i = tid; i < 1024; i += BLK) { sW1[i] = W1[i]; sW2[i] = W2[i]; }
    if (tid < 16) {
        sB1[tid] = pk2(b1[2 * tid], b1[2 * tid + 1]);
        sB2[tid] = pk2(b2[2 * tid], b2[2 * tid + 1]);
    }
    __syncthreads();

    int i = blockIdx.x * BLK + tid;
    if (i >= NN) return;

    // ---- assemble y = [h_n(10) | sent(10) | recv(10) | g(2)] ----
    float n0 = nodes[2 * i + 0];
    float n1 = nodes[2 * i + 1];
    float4 sa = g_agg[i];
    float4 ra = g_agg[NN + i];
    float y[32];
#pragma unroll
    for (int c = 0; c < 10; c++) {
        y[c] = fmaf(n0, __ldg(&encNW[c]), fmaf(n1, __ldg(&encNW[10 + c]), __ldg(&encNb[c])));
        float we0 = __ldg(&encEW[c]), we1 = __ldg(&encEW[10 + c]);
        float we2 = __ldg(&encEW[20 + c]), web = __ldg(&encEb[c]);
        y[10 + c] = fmaf(sa.x, we0, fmaf(sa.y, we1, fmaf(sa.z, we2, sa.w * web)));
        y[20 + c] = fmaf(ra.x, we0, fmaf(ra.y, we1, fmaf(ra.z, we2, ra.w * web)));
    }
    y[30] = gl[0];
    y[31] = gl[1];

    ull y2[16], yn2[16], acc[16];
#pragma unroll
    for (int p = 0; p < 16; p++) y2[p] = pk2(y[2 * p], y[2 * p + 1]);

    // Dopri5 coefficients pre-scaled by H=0.1, packed as f32x2
    const ull cA21 = cpk((float)(0.1 * (1.0 / 5.0)));
    const ull cA31 = cpk((float)(0.1 * (3.0 / 40.0)));
    const ull cA32 = cpk((float)(0.1 * (9.0 / 40.0)));
    const ull cA41 = cpk((float)(0.1 * (44.0 / 45.0)));
    const ull cA42 = cpk((float)(0.1 * (-56.0 / 15.0)));
    const ull cA43 = cpk((float)(0.1 * (32.0 / 9.0)));
    const ull cA51 = cpk((float)(0.1 * (19372.0 / 6561.0)));
    const ull cA52 = cpk((float)(0.1 * (-25360.0 / 2187.0)));
    const ull cA53 = cpk((float)(0.1 * (64448.0 / 6561.0)));
    const ull cA54 = cpk((float)(0.1 * (-212.0 / 729.0)));
    const ull cA61 = cpk((float)(0.1 * (9017.0 / 3168.0)));
    const ull cA62 = cpk((float)(0.1 * (-355.0 / 33.0)));
    const ull cA63 = cpk((float)(0.1 * (46732.0 / 5247.0)));
    const ull cA64 = cpk((float)(0.1 * (49.0 / 176.0)));
    const ull cA65 = cpk((float)(0.1 * (-5103.0 / 18656.0)));
    const ull cB1  = cpk((float)(0.1 * (35.0 / 384.0)));
    const ull cB3  = cpk((float)(0.1 * (500.0 / 1113.0)));
    const ull cB4  = cpk((float)(0.1 * (125.0 / 192.0)));
    const ull cB5  = cpk((float)(0.1 * (-2187.0 / 6784.0)));
    const ull cB6  = cpk((float)(0.1 * (11.0 / 84.0)));

#define KS(s, p) sK[(((s) * 16) + (p)) * BLK + tid]

#pragma unroll 1
    for (int st = 0; st < 10; ++st) {
#pragma unroll
        for (int p = 0; p < 16; p++) sTmp[p * BLK + tid] = y2[p];
        odef(sW1, sW2, sB1, sB2, sTmp, tid, acc);            // k1
#pragma unroll
        for (int p = 0; p < 16; p++) {
            KS(0, p) = acc[p];
            yn2[p] = f2fma(acc[p], cB1, y2[p]);
            sTmp[p * BLK + tid] = f2fma(acc[p], cA21, y2[p]);
        }
        odef(sW1, sW2, sB1, sB2, sTmp, tid, acc);            // k2
#pragma unroll
        for (int p = 0; p < 16; p++) {
            KS(1, p) = acc[p];
            ull t = f2fma(KS(0, p), cA31, y2[p]);
            sTmp[p * BLK + tid] = f2fma(acc[p], cA32, t);
        }
        odef(sW1, sW2, sB1, sB2, sTmp, tid, acc);            // k3
#pragma unroll
        for (int p = 0; p < 16; p++) {
            KS(2, p) = acc[p];
            yn2[p] = f2fma(acc[p], cB3, yn2[p]);
            ull t = f2fma(KS(0, p), cA41, y2[p]);
            t = f2fma(KS(1, p), cA42, t);
            sTmp[p * BLK + tid] = f2fma(acc[p], cA43, t);
        }
        odef(sW1, sW2, sB1, sB2, sTmp, tid, acc);            // k4
#pragma unroll
        for (int p = 0; p < 16; p++) {
            KS(3, p) = acc[p];
            yn2[p] = f2fma(acc[p], cB4, yn2[p]);
            ull t = f2fma(KS(0, p), cA51, y2[p]);
            t = f2fma(KS(1, p), cA52, t);
            t = f2fma(KS(2, p), cA53, t);
            sTmp[p * BLK + tid] = f2fma(acc[p], cA54, t);
        }
        odef(sW1, sW2, sB1, sB2, sTmp, tid, acc);            // k5 (never stored)
#pragma unroll
        for (int p = 0; p < 16; p++) {
            yn2[p] = f2fma(acc[p], cB5, yn2[p]);
            ull t = f2fma(KS(0, p), cA61, y2[p]);
            t = f2fma(KS(1, p), cA62, t);
            t = f2fma(KS(2, p), cA63, t);
            t = f2fma(KS(3, p), cA64, t);
            sTmp[p * BLK + tid] = f2fma(acc[p], cA65, t);
        }
        odef(sW1, sW2, sB1, sB2, sTmp, tid, acc);            // k6
#pragma unroll
        for (int p = 0; p < 16; p++) y2[p] = f2fma(acc[p], cB6, yn2[p]);
    }
#undef KS

    // ---- fused decode + integrator output ----
    float dec = g_prep[36];
#pragma unroll
    for (int p = 0; p < 16; p++) {
        float lo, hi;
        upk2(y2[p], lo, hi);
        dec = fmaf(lo, g_prep[4 + 2 * p], dec);
        dec = fmaf(hi, g_prep[5 + 2 * p], dec);
    }
    out[i] = dec;
    float vel = n1 + dec;
    out[OUT_VEL + i] = vel;
    out[OUT_POS + i] = n0 + vel;
}

extern "C" void kernel_launch(void* const* d_in, const int* in_sizes, int n_in,
                              void* d_out, int out_size) {
    const float* nodes     = (const float*)d_in[0];
    const float* edges     = (const float*)d_in[1];
    const int*   senders   = (const int*)d_in[2];
    const int*   receivers = (const int*)d_in[3];
    const float* globals_  = (const float*)d_in[4];
    const float* encNW     = (const float*)d_in[5];
    const float* encNb     = (const float*)d_in[6];
    const float* encEW     = (const float*)d_in[7];
    const float* encEb     = (const float*)d_in[8];
    const float* odeW1     = (const float*)d_in[9];
    const float* odeb1     = (const float*)d_in[10];
    const float* odeW2     = (const float*)d_in[11];
    const float* odeb2     = (const float*)d_in[12];
    const float* noW       = (const float*)d_in[13];
    const float* nob       = (const float*)d_in[14];
    const float* decNW     = (const float*)d_in[15];
    const float* decNb     = (const float*)d_in[16];
    const float* decEW     = (const float*)d_in[17];
    const float* decEb     = (const float*)d_in[18];
    float* out = (float*)d_out;

    prep_kernel<<<1, 64>>>(encEW, encEb, decEW, decEb, noW, nob, decNW, decNb);
    zero_kernel<<<(2 * NN + 255) / 256, 256>>>();
    edge_kernel<<<(NE + 255) / 256, 256>>>(edges, senders, receivers, out);
    ode_kernel<<<(NN + BLK - 1) / BLK, BLK>>>(nodes, globals_, encNW, encNb, encEW, encEb,
                                              odeW1, odeb1, odeW2, odeb2, out);
}

// round 2
// speedup vs baseline: 1.2212x; 1.2212x over previous
#include <cuda_runtime.h>
#include <cstdint>

#define NN 100000
#define NE 1600000
#define OUT_DECE (NN)
#define OUT_POS  (NN + NE)
#define OUT_VEL  (NN + NE + NN)
#define BLK 32

typedef unsigned long long ull;

// ---------------- device-global scratch (no allocations allowed) ----------------
__device__ float4 g_agg[2 * NN];   // [0,NN): sender sums {e0,e1,e2,count}; [NN,2NN): receiver
__device__ float  g_prep[40];      // [0..2]=c_edge, [3]=d_edge, [4..35]=p(node dec), [36]=q
// RK coefficient tables (packed f32x2, premultiplied by H, rebased onto yn accumulator)
__device__ ull g_B[6];             // yn += B[s] * k_{s+1}
__device__ ull g_CR[6];            // coefficient of current-stage k (in regs)
__device__ ull g_CS[24];           // [s*4+j]: coefficient of smem k_{j+1} for stage s
__device__ ull g_bpk1[16];         // channel-packed biases for ODE layer 1
__device__ ull g_bpk2[16];         // layer 2

// ---------------- packed f32x2 helpers ----------------
__device__ __forceinline__ ull pk2(float lo, float hi) {
    ull r;
    asm("mov.b64 %0, {%1, %2};" : "=l"(r) : "r"(__float_as_uint(lo)), "r"(__float_as_uint(hi)));
    return r;
}
__device__ __forceinline__ void upk2(ull v, float& lo, float& hi) {
    unsigned a, b;
    asm("mov.b64 {%0, %1}, %2;" : "=r"(a), "=r"(b) : "l"(v));
    lo = __uint_as_float(a); hi = __uint_as_float(b);
}
__device__ __forceinline__ ull f2fma(ull a, ull b, ull c) {
    ull d;
    asm("fma.rn.f32x2 %0, %1, %2, %3;" : "=l"(d) : "l"(a), "l"(b), "l"(c));
    return d;
}
__device__ __forceinline__ ull cpkd(float x) {
    unsigned u = __float_as_uint(x);
    return (((ull)u) << 32) | (ull)u;
}

// ---------------- precompute kernel ----------------
__global__ void prep_kernel(const float* __restrict__ eW, const float* __restrict__ eb,
                            const float* __restrict__ decEW, const float* __restrict__ decEb,
                            const float* __restrict__ noW, const float* __restrict__ nob,
                            const float* __restrict__ decNW, const float* __restrict__ decNb,
                            const float* __restrict__ ob1, const float* __restrict__ ob2) {
    int t = threadIdx.x;
    if (t < 3) {
        float s = 0.f;
        for (int c = 0; c < 10; c++) s += eW[t * 10 + c] * decEW[c];
        g_prep[t] = s;
    } else if (t == 3) {
        float s = decEb[0];
        for (int c = 0; c < 10; c++) s += eb[c] * decEW[c];
        g_prep[3] = s;
    } else if (t >= 4 && t < 36) {
        int j = t - 4;
        float s = 0.f;
        for (int c = 0; c < 10; c++) s += noW[j * 10 + c] * decNW[c];
        g_prep[t] = s;
    } else if (t == 36) {
        float s = decNb[0];
        for (int c = 0; c < 10; c++) s += nob[c] * decNW[c];
        g_prep[36] = s;
    } else if (t == 37) {
        // RK tables
        const double Hd = 0.1;
        const double B1 = 35.0/384.0, B3 = 500.0/1113.0, B4 = 125.0/192.0,
                     B5 = -2187.0/6784.0, B6 = 11.0/84.0;
        const double A21 = 1.0/5.0;
        const double A31 = 3.0/40.0, A32 = 9.0/40.0;
        const double A41 = 44.0/45.0, A42 = -56.0/15.0, A43 = 32.0/9.0;
        const double A51 = 19372.0/6561.0, A52 = -25360.0/2187.0,
                     A53 = 64448.0/6561.0, A54 = -212.0/729.0;
        const double A61 = 9017.0/3168.0, A62 = -355.0/33.0, A63 = 46732.0/5247.0,
                     A64 = 49.0/176.0, A65 = -5103.0/18656.0;
        g_B[0] = cpkd((float)(Hd * B1));
        g_B[1] = 0ull;
        g_B[2] = cpkd((float)(Hd * B3));
        g_B[3] = cpkd((float)(Hd * B4));
        g_B[4] = cpkd((float)(Hd * B5));
        g_B[5] = cpkd((float)(Hd * B6));
        g_CR[0] = cpkd((float)(Hd * (A21 - B1)));
        g_CR[1] = cpkd((float)(Hd * A32));
        g_CR[2] = cpkd((float)(Hd * (A43 - B3)));
        g_CR[3] = cpkd((float)(Hd * (A54 - B4)));
        g_CR[4] = cpkd((float)(Hd * (A65 - B5)));
        g_CR[5] = 0ull;
        for (int i = 0; i < 24; i++) g_CS[i] = 0ull;
        g_CS[1 * 4 + 0] = cpkd((float)(Hd * (A31 - B1)));
        g_CS[2 * 4 + 0] = cpkd((float)(Hd * (A41 - B1)));
        g_CS[2 * 4 + 1] = cpkd((float)(Hd * A42));
        g_CS[3 * 4 + 0] = cpkd((float)(Hd * (A51 - B1)));
        g_CS[3 * 4 + 1] = cpkd((float)(Hd * A52));
        g_CS[3 * 4 + 2] = cpkd((float)(Hd * (A53 - B3)));
        g_CS[4 * 4 + 0] = cpkd((float)(Hd * (A61 - B1)));
        g_CS[4 * 4 + 1] = cpkd((float)(Hd * A62));
        g_CS[4 * 4 + 2] = cpkd((float)(Hd * (A63 - B3)));
        g_CS[4 * 4 + 3] = cpkd((float)(Hd * (A64 - B4)));
    } else if (t >= 38 && t < 54) {
        int p = t - 38;
        g_bpk1[p] = pk2(ob1[2 * p], ob1[2 * p + 1]);
        g_bpk2[p] = pk2(ob2[2 * p], ob2[2 * p + 1]);
    }
}

__global__ void zero_kernel() {
    int i = blockIdx.x * blockDim.x + threadIdx.x;
    if (i < 2 * NN) g_agg[i] = make_float4(0.f, 0.f, 0.f, 0.f);
}

// ---------------- edge kernel ----------------
__global__ void edge_kernel(const float* __restrict__ edges,
                            const int* __restrict__ senders,
                            const int* __restrict__ receivers,
                            float* __restrict__ out) {
    int e = blockIdx.x * blockDim.x + threadIdx.x;
    if (e >= NE) return;
    float e0 = edges[3 * e + 0];
    float e1 = edges[3 * e + 1];
    float e2 = edges[3 * e + 2];
    int s = senders[e];
    int r = receivers[e];
    float c0 = g_prep[0], c1 = g_prep[1], c2 = g_prep[2], d = g_prep[3];
    out[OUT_DECE + e] = fmaf(e0, c0, fmaf(e1, c1, fmaf(e2, c2, d)));

    float4* ps = &g_agg[s];
    float4* pr = &g_agg[NN + r];
    asm volatile("red.global.add.v4.f32 [%0], {%1, %2, %3, %4};"
                 :: "l"(ps), "f"(e0), "f"(e1), "f"(e2), "f"(1.0f) : "memory");
    asm volatile("red.global.add.v4.f32 [%0], {%1, %2, %3, %4};"
                 :: "l"(pr), "f"(e0), "f"(e1), "f"(e2), "f"(1.0f) : "memory");
}

// ---------------- ODE kernel: 2 nodes/thread, channel-packed f32x2 ----------------
// mm for 2 nodes: (ha,hb) = bias + (ua,ub) @ W.  Weight loads amortized over both nodes.
__device__ __forceinline__ void mm2(const float* __restrict__ sW, const ull* __restrict__ gBpk,
                                    const ull* __restrict__ ua, const ull* __restrict__ ub,
                                    ull* __restrict__ ha, ull* __restrict__ hb) {
#pragma unroll
    for (int p = 0; p < 16; p++) { ull bb = __ldg(&gBpk[p]); ha[p] = bb; hb[p] = bb; }
#pragma unroll
    for (int ii = 0; ii < 16; ++ii) {
        float la, hA_, lb, hB_;
        upk2(ua[ii], la, hA_);
        upk2(ub[ii], lb, hB_);
        ull vla = pk2(la, la), vha = pk2(hA_, hA_);
        ull vlb = pk2(lb, lb), vhb = pk2(hB_, hB_);
        const ulonglong2* w0 = reinterpret_cast<const ulonglong2*>(sW + ii * 64);
#pragma unroll
        for (int q = 0; q < 8; q++) {
            ulonglong2 a = w0[q];
            ha[2 * q]     = f2fma(a.x, vla, ha[2 * q]);
            ha[2 * q + 1] = f2fma(a.y, vla, ha[2 * q + 1]);
            hb[2 * q]     = f2fma(a.x, vlb, hb[2 * q]);
            hb[2 * q + 1] = f2fma(a.y, vlb, hb[2 * q + 1]);
        }
        const ulonglong2* w1 = reinterpret_cast<const ulonglong2*>(sW + ii * 64 + 32);
#pragma unroll
        for (int q = 0; q < 8; q++) {
            ulonglong2 a = w1[q];
            ha[2 * q]     = f2fma(a.x, vha, ha[2 * q]);
            ha[2 * q + 1] = f2fma(a.y, vha, ha[2 * q + 1]);
            hb[2 * q]     = f2fma(a.x, vhb, hb[2 * q]);
            hb[2 * q + 1] = f2fma(a.y, vhb, hb[2 * q + 1]);
        }
    }
}

__global__ __launch_bounds__(BLK)
void ode_kernel(const float* __restrict__ nodes, const float* __restrict__ gl,
                const float* __restrict__ encNW, const float* __restrict__ encNb,
                const float* __restrict__ encEW, const float* __restrict__ encEb,
                const float* __restrict__ W1, const float* __restrict__ W2,
                float* __restrict__ out) {
    __shared__ __align__(16) float sW1[1024];
    __shared__ __align__(16) float sW2[1024];
    __shared__ __align__(16) ull sYn[16 * 64];      // [p][pairNode] per-thread-private slots
    __shared__ __align__(16) ull sK[4 * 16 * 64];   // k1..k4

    int t = threadIdx.x;
    for (int i = t; i < 1024; i += BLK) { sW1[i] = W1[i]; sW2[i] = W2[i]; }
    __syncwarp();

    int base = blockIdx.x * 64;
    int A = base + t;
    int B = base + t + 32;
    bool bok = (B < NN);

    // ---- encoder for both nodes ----
    float2 nA = reinterpret_cast<const float2*>(nodes)[A];
    float2 nB = bok ? reinterpret_cast<const float2*>(nodes)[B] : make_float2(0.f, 0.f);
    float4 z4 = make_float4(0.f, 0.f, 0.f, 0.f);
    float4 saA = g_agg[A], raA = g_agg[NN + A];
    float4 saB = bok ? g_agg[B] : z4;
    float4 raB = bok ? g_agg[NN + B] : z4;

    float yA[32], yB[32];
#pragma unroll
    for (int c = 0; c < 10; c++) {
        float wn0 = __ldg(&encNW[c]), wn1 = __ldg(&encNW[10 + c]), bn = __ldg(&encNb[c]);
        yA[c] = fmaf(nA.x, wn0, fmaf(nA.y, wn1, bn));
        yB[c] = fmaf(nB.x, wn0, fmaf(nB.y, wn1, bn));
        float we0 = __ldg(&encEW[c]), we1 = __ldg(&encEW[10 + c]);
        float we2 = __ldg(&encEW[20 + c]), web = __ldg(&encEb[c]);
        yA[10 + c] = fmaf(saA.x, we0, fmaf(saA.y, we1, fmaf(saA.z, we2, saA.w * web)));
        yB[10 + c] = fmaf(saB.x, we0, fmaf(saB.y, we1, fmaf(saB.z, we2, saB.w * web)));
        yA[20 + c] = fmaf(raA.x, we0, fmaf(raA.y, we1, fmaf(raA.z, we2, raA.w * web)));
        yB[20 + c] = fmaf(raB.x, we0, fmaf(raB.y, we1, fmaf(raB.z, we2, raB.w * web)));
    }
    float g0 = gl[0], g1 = gl[1];
    yA[30] = g0; yA[31] = g1; yB[30] = g0; yB[31] = g1;

    ull uA[16], uB[16];
#pragma unroll
    for (int p = 0; p < 16; p++) {
        uA[p] = pk2(yA[2 * p], yA[2 * p + 1]);
        uB[p] = pk2(yB[2 * p], yB[2 * p + 1]);
    }
    // init yn accumulator = y
#pragma unroll
    for (int p = 0; p < 16; p++)
        *reinterpret_cast<ulonglong2*>(&sYn[p * 64 + 2 * t]) = make_ulonglong2(uA[p], uB[p]);

    // ---- 10 Dopri5 steps ----
#pragma unroll 1
    for (int st = 0; st < 10; ++st) {
#pragma unroll 1
        for (int s = 0; s < 6; ++s) {
            ull hA[16], hB[16], kA[16], kB[16];
            mm2(sW1, g_bpk1, uA, uB, hA, hB);
#pragma unroll
            for (int p = 0; p < 16; p++) {
                float lo, hi;
                upk2(hA[p], lo, hi);
                hA[p] = pk2(fmaxf(lo, 0.f), fmaxf(hi, 0.f));
                upk2(hB[p], lo, hi);
                hB[p] = pk2(fmaxf(lo, 0.f), fmaxf(hi, 0.f));
            }
            mm2(sW2, g_bpk2, hA, hB, kA, kB);   // kA/kB = k_{s+1}

            // ---- stage end: yn update + next-stage input (into uA/uB) ----
            ull b = __ldg(&g_B[s]);
#pragma unroll
            for (int p = 0; p < 16; p++) {
                ulonglong2 v = *reinterpret_cast<const ulonglong2*>(&sYn[p * 64 + 2 * t]);
                uA[p] = v.x; uB[p] = v.y;
            }
            if (b != 0ull) {
#pragma unroll
                for (int p = 0; p < 16; p++) {
                    uA[p] = f2fma(kA[p], b, uA[p]);
                    uB[p] = f2fma(kB[p], b, uB[p]);
                }
#pragma unroll
                for (int p = 0; p < 16; p++)
                    *reinterpret_cast<ulonglong2*>(&sYn[p * 64 + 2 * t]) =
                        make_ulonglong2(uA[p], uB[p]);
            }
            if (s < 5) {
#pragma unroll 1
                for (int j = 0; j < s; ++j) {
                    ull c = __ldg(&g_CS[s * 4 + j]);
#pragma unroll
                    for (int p = 0; p < 16; p++) {
                        ulonglong2 v = *reinterpret_cast<const ulonglong2*>(
                            &sK[(j * 16 + p) * 64 + 2 * t]);
                        uA[p] = f2fma(v.x, c, uA[p]);
                        uB[p] = f2fma(v.y, c, uB[p]);
                    }
                }
                ull cr = __ldg(&g_CR[s]);
#pragma unroll
                for (int p = 0; p < 16; p++) {
                    uA[p] = f2fma(kA[p], cr, uA[p]);
                    uB[p] = f2fma(kB[p], cr, uB[p]);
                }
                if (s < 4) {
#pragma unroll
                    for (int p = 0; p < 16; p++)
                        *reinterpret_cast<ulonglong2*>(&sK[(s * 16 + p) * 64 + 2 * t]) =
                            make_ulonglong2(kA[p], kB[p]);
                }
            }
            // s == 5: uA/uB = y_new (also stored to sYn above since g_B[5] != 0)
        }
    }

    // ---- fused decode + integrator epilogue ----
    float q = __ldg(&g_prep[36]);
    float decA = q, decB = q;
#pragma unroll
    for (int p = 0; p < 16; p++) {
        float pl = __ldg(&g_prep[4 + 2 * p]);
        float ph = __ldg(&g_prep[5 + 2 * p]);
        float lo, hi;
        upk2(uA[p], lo, hi);
        decA = fmaf(lo, pl, fmaf(hi, ph, decA));
        upk2(uB[p], lo, hi);
        decB = fmaf(lo, pl, fmaf(hi, ph, decB));
    }
    out[A] = decA;
    float velA = nA.y + decA;
    out[OUT_VEL + A] = velA;
    out[OUT_POS + A] = nA.x + velA;
    if (bok) {
        out[B] = decB;
        float velB = nB.y + decB;
        out[OUT_VEL + B] = velB;
        out[OUT_POS + B] = nB.x + velB;
    }
}

extern "C" void kernel_launch(void* const* d_in, const int* in_sizes, int n_in,
                              void* d_out, int out_size) {
    const float* nodes     = (const float*)d_in[0];
    const float* edges     = (const float*)d_in[1];
    const int*   senders   = (const int*)d_in[2];
    const int*   receivers = (const int*)d_in[3];
    const float* globals_  = (const float*)d_in[4];
    const float* encNW     = (const float*)d_in[5];
    const float* encNb     = (const float*)d_in[6];
    const float* encEW     = (const float*)d_in[7];
    const float* encEb     = (const float*)d_in[8];
    const float* odeW1     = (const float*)d_in[9];
    const float* odeb1     = (const float*)d_in[10];
    const float* odeW2     = (const float*)d_in[11];
    const float* odeb2     = (const float*)d_in[12];
    const float* noW       = (const float*)d_in[13];
    const float* nob       = (const float*)d_in[14];
    const float* decNW     = (const float*)d_in[15];
    const float* decNb     = (const float*)d_in[16];
    const float* decEW     = (const float*)d_in[17];
    const float* decEb     = (const float*)d_in[18];
    float* out = (float*)d_out;

    prep_kernel<<<1, 64>>>(encEW, encEb, decEW, decEb, noW, nob, decNW, decNb, odeb1, odeb2);
    zero_kernel<<<(2 * NN + 255) / 256, 256>>>();
    edge_kernel<<<(NE + 255) / 256, 256>>>(edges, senders, receivers, out);
    int nblk = (NN + 63) / 64;
    ode_kernel<<<nblk, BLK>>>(nodes, globals_, encNW, encNb, encEW, encEb,
                              odeW1, odeW2, out);
}